// round 1
// baseline (speedup 1.0000x reference)
#include <cuda_runtime.h>
#include <cstdint>

#define N1 16384
#define N2 16384
#define G1 4
#define G2 38
#define CHUNK1 4096          // N1 / G1
#define CHUNK2 432           // ceil(N2 / G2): 38*432 = 16416 >= 16384
#define THREADS 256
#define PP 8                 // packed f32x2 lanes per thread -> 16 pos1 points

// Per-pos1 running min of squared distance, stored as uint bits (monotone for >=0 floats)
__device__ unsigned int g_min_bits[N1];

__device__ __forceinline__ unsigned long long dup_f32(float v) {
    unsigned int u = __float_as_uint(v);
    return ((unsigned long long)u << 32) | (unsigned long long)u;
}

__device__ __forceinline__ unsigned long long pack2(float lo, float hi) {
    unsigned long long d;
    asm("mov.b64 %0, {%1, %2};" : "=l"(d) : "r"(__float_as_uint(lo)), "r"(__float_as_uint(hi)));
    return d;
}

__device__ __forceinline__ void unpack2(unsigned long long v, float& lo, float& hi) {
    unsigned int a, b;
    asm("mov.b64 {%0, %1}, %2;" : "=r"(a), "=r"(b) : "l"(v));
    lo = __uint_as_float(a);
    hi = __uint_as_float(b);
}

__device__ __forceinline__ unsigned long long fma_f32x2(unsigned long long a,
                                                        unsigned long long b,
                                                        unsigned long long c) {
    unsigned long long d;
    asm("fma.rn.f32x2 %0, %1, %2, %3;" : "=l"(d) : "l"(a), "l"(b), "l"(c));
    return d;
}

__global__ void init_kernel() {
    int i = blockIdx.x * blockDim.x + threadIdx.x;
    if (i < N1) g_min_bits[i] = 0x7f800000u;  // +inf
}

__global__ __launch_bounds__(THREADS, 1)
void nn_kernel(const float* __restrict__ pos1, const float* __restrict__ pos2) {
    // Per pos2 point: {x2|x2, y2|y2, sn|sn, pad} where x2=-2x, y2=-2y, sn=x^2+y^2.
    // 32B stride per point; scalars pre-duplicated so the inner loop needs no packing.
    __shared__ unsigned long long sh[CHUNK2 * 4];

    const int tid   = threadIdx.x;
    const int base2 = blockIdx.x * CHUNK2;
    const int base1 = blockIdx.y * CHUNK1;

    for (int j = tid; j < CHUNK2; j += THREADS) {
        int idx = base2 + j;
        float x2, y2, sn;
        if (idx < N2) {
            float x = pos2[2 * idx + 0];
            float y = pos2[2 * idx + 1];
            x2 = -2.0f * x;
            y2 = -2.0f * y;
            sn = fmaf(x, x, y * y);
        } else {
            // sentinel: t = fma(px,0, fma(py,0, inf)) = +inf, never selected
            x2 = 0.0f; y2 = 0.0f; sn = __uint_as_float(0x7f800000u);
        }
        sh[4 * j + 0] = dup_f32(x2);
        sh[4 * j + 1] = dup_f32(y2);
        sh[4 * j + 2] = dup_f32(sn);
    }

    // Load 16 pos1 points per thread (coalesced, stride THREADS), pack lanes (k, k+8).
    unsigned long long PX[PP], PY[PP];
    float m[16];
    {
        float px[16], py[16];
#pragma unroll
        for (int k = 0; k < 16; k++) {
            int idx = base1 + tid + k * THREADS;
            px[k] = pos1[2 * idx + 0];
            py[k] = pos1[2 * idx + 1];
            m[k] = __uint_as_float(0x7f800000u);
        }
#pragma unroll
        for (int k = 0; k < PP; k++) {
            PX[k] = pack2(px[k], px[k + 8]);
            PY[k] = pack2(py[k], py[k + 8]);
        }
    }
    __syncthreads();

#pragma unroll 2
    for (int j = 0; j < CHUNK2; j++) {
        unsigned long long X = sh[4 * j + 0];
        unsigned long long Y = sh[4 * j + 1];
        unsigned long long S = sh[4 * j + 2];
#pragma unroll
        for (int k = 0; k < PP; k++) {
            unsigned long long t = fma_f32x2(PY[k], Y, S);
            t = fma_f32x2(PX[k], X, t);
            float lo, hi;
            unpack2(t, lo, hi);
            m[k]      = fminf(m[k],      lo);
            m[k + 8]  = fminf(m[k + 8],  hi);
        }
    }

    // Epilogue: d2 = |p|^2 + min_t, clamp >= 0, fold into global min.
#pragma unroll
    for (int k = 0; k < PP; k++) {
        float xlo, xhi, ylo, yhi;
        unpack2(PX[k], xlo, xhi);
        unpack2(PY[k], ylo, yhi);
        {
            int idx  = base1 + tid + k * THREADS;
            float pn = fmaf(xlo, xlo, ylo * ylo);
            float d2 = fmaxf(pn + m[k], 0.0f);
            atomicMin(&g_min_bits[idx], __float_as_uint(d2));
        }
        {
            int idx  = base1 + tid + (k + 8) * THREADS;
            float pn = fmaf(xhi, xhi, yhi * yhi);
            float d2 = fmaxf(pn + m[k + 8], 0.0f);
            atomicMin(&g_min_bits[idx], __float_as_uint(d2));
        }
    }
}

__global__ void reduce_kernel(float* __restrict__ out) {
    __shared__ float red[512];
    int tid = threadIdx.x;
    float s = 0.0f;
    for (int i = tid; i < N1; i += 512) {
        s += sqrtf(__uint_as_float(g_min_bits[i]));
    }
    red[tid] = s;
    __syncthreads();
    for (int w = 256; w > 0; w >>= 1) {
        if (tid < w) red[tid] += red[tid + w];
        __syncthreads();
    }
    if (tid == 0) out[0] = red[0] * (1.0f / (float)N1);
}

extern "C" void kernel_launch(void* const* d_in, const int* in_sizes, int n_in,
                              void* d_out, int out_size) {
    const float* pos1 = (const float*)d_in[0];
    const float* pos2 = (const float*)d_in[1];
    float* out = (float*)d_out;

    init_kernel<<<N1 / 256, 256>>>();
    dim3 grid(G2, G1);
    nn_kernel<<<grid, THREADS>>>(pos1, pos2);
    reduce_kernel<<<1, 512>>>(out);
}